// round 14
// baseline (speedup 1.0000x reference)
#include <cuda_runtime.h>
#include <cuda_bf16.h>
#include <math.h>
#include <stdint.h>

#define N_NODES 50000
#define N_EDGES 400000
#define D_EMB   512
#define HEADS   8
#define DK      32
#define DV      32
#define HD      (HEADS * DK)   // 256
#define KQVS    768            // merged packed row: [h:K32|V32]x8 | Q 256

#define M_SPLIT 25088          // 196 tiles of 128; half B = 24912 rows (195 tiles)

// ---------------- scratch (device globals; no allocations allowed) ----------
__device__ float g_bkqv[KQVS];
__device__ int   g_cnt[N_NODES];
__device__ int   g_off[N_NODES + 1];
__device__ int   g_cur[N_NODES];
__device__ int   g_csr[N_EDGES];               // sender ids grouped by receiver
__device__ __nv_bfloat16 g_kqvb[N_NODES * KQVS];   // packed bf16 K|V per head, then Q
__device__ __nv_bfloat16 g_xb[N_NODES * D_EMB];
__device__ __nv_bfloat16 g_aggb[N_NODES * HD];
__device__ __nv_bfloat16 g_h1b[N_NODES * D_EMB];
__device__ __nv_bfloat16 g_wtb[786432];        // W^T bf16: kqv(perm) | Wa | Wf

#define OFF_WKQV 0
#define OFF_WA   393216
#define OFF_WF   524288

// ---------------- CSR build --------------------------------------------------
__global__ void zero_cnt_kernel() {
    int i = blockIdx.x * blockDim.x + threadIdx.x;
    if (i < N_NODES) g_cnt[i] = 0;
}
__global__ void hist_kernel(const int* __restrict__ ei) {
    int e = blockIdx.x * blockDim.x + threadIdx.x;
    if (e >= N_EDGES) return;
    atomicAdd(&g_cnt[ei[e]], 1);
}
__global__ __launch_bounds__(1024)
void scan_kernel() {
    __shared__ int partial[1024];
    const int t  = threadIdx.x;
    const int CH = (N_NODES + 1023) / 1024;   // 49
    const int base = t * CH;
    int sum = 0;
    for (int i = 0; i < CH; i++) {
        int idx = base + i;
        if (idx < N_NODES) sum += g_cnt[idx];
    }
    partial[t] = sum;
    __syncthreads();
    for (int d = 1; d < 1024; d <<= 1) {
        int v = (t >= d) ? partial[t - d] : 0;
        __syncthreads();
        partial[t] += v;
        __syncthreads();
    }
    int run = (t > 0) ? partial[t - 1] : 0;
    for (int i = 0; i < CH; i++) {
        int idx = base + i;
        if (idx < N_NODES) {
            int c = g_cnt[idx];
            g_off[idx] = run;
            g_cur[idx] = run;
            run += c;
        }
    }
    if (t == 1023) g_off[N_NODES] = partial[1023];
}
__global__ void place_kernel(const int* __restrict__ ei) {
    int e = blockIdx.x * blockDim.x + threadIdx.x;
    if (e >= N_EDGES) return;
    int r = ei[e];
    int s = ei[N_EDGES + e];
    int pos = atomicAdd(&g_cur[r], 1);
    g_csr[pos] = s;
}

// ---------------- prep: ALL weights -> gWtb [n][k] bf16 (one launch) ---------
__global__ void wt_all_cvt_kernel(const float* __restrict__ Wk,
                                  const float* __restrict__ Wq,
                                  const float* __restrict__ Wv,
                                  const float* __restrict__ Wa,
                                  const float* __restrict__ Wf) {
    int j = blockIdx.x * blockDim.x + threadIdx.x;
    if (j >= 786432) return;
    float v;
    if (j < 393216) {                 // kqv: rows 768, cols 512
        int n = j >> 9;               // j / 512
        int k = j & 511;
        if (n < 512) {
            int h = n >> 6, r = n & 63;
            v = (r < 32) ? Wk[(size_t)k * 256 + h * 32 + r]
                         : Wv[(size_t)k * 256 + h * 32 + (r - 32)];
        } else {
            v = Wq[(size_t)k * 256 + (n - 512)];
        }
    } else if (j < 524288) {          // Wa^T: rows 512, cols 256
        int jj = j - 393216;
        int n = jj >> 8;
        int k = jj & 255;
        v = Wa[(size_t)k * 512 + n];
    } else {                          // Wf^T: rows 512, cols 512
        int jj = j - 524288;
        int n = jj >> 9;
        int k = jj & 511;
        v = Wf[(size_t)k * 512 + n];
    }
    g_wtb[j] = __float2bfloat16_rn(v);
}

__global__ void cvt_bf16_kernel(const float* __restrict__ src,
                                __nv_bfloat16* __restrict__ dst, int n4) {
    int i = blockIdx.x * blockDim.x + threadIdx.x;
    if (i >= n4) return;
    float4 v = *(const float4*)(src + i * 4);
    __nv_bfloat162 a = __float22bfloat162_rn(make_float2(v.x, v.y));
    __nv_bfloat162 b = __float22bfloat162_rn(make_float2(v.z, v.w));
    *(uint32_t*)(dst + i * 4)     = *(uint32_t*)&a;
    *(uint32_t*)(dst + i * 4 + 2) = *(uint32_t*)&b;
}

__global__ void bias_concat_kernel(const float* bk, const float* bq,
                                   const float* bv) {
    int n = threadIdx.x + blockIdx.x * blockDim.x;
    if (n >= KQVS) return;
    float v;
    if (n < 512) {
        int h = n >> 6, r = n & 63;
        v = (r < 32) ? bk[h * 32 + r] : bv[h * 32 + (r - 32)];
    } else {
        v = bq[n - 512];
    }
    g_bkqv[n] = v;
}

// ---------------- bf16 GEMM: cp.async 4-stage + ldmatrix ---------------------
#define STAGES 4
#define KTILE  32
#define RS     40
#define AE     (128 * RS)
#define STE    (2 * AE)
#define GEMM_SMEM (STAGES * STE * 2)  // 81920 bytes

template<bool RELU_OUT, bool OUT_BF16, bool RES>
__global__ __launch_bounds__(256, 2)
void bf16gemm(const __nv_bfloat16* __restrict__ A,
              const __nv_bfloat16* __restrict__ B,
              const float* __restrict__ bias, const float* __restrict__ res,
              void* __restrict__ Cv, int M, int N, int K)
{
    extern __shared__ __nv_bfloat16 S[];
    const uint32_t sbase = (uint32_t)__cvta_generic_to_shared(S);

    const int tid  = threadIdx.x;
    const int lane = tid & 31;
    const int wid  = tid >> 5;
    const int wm   = (wid & 1) * 64;
    const int wn   = (wid >> 1) * 32;

    const int row0 = blockIdx.y * 128;
    const int col0 = blockIdx.x * 128;

    const int fr = lane >> 2;
    const int fc = lane & 3;

    const int a_off = (lane & 15) * RS + ((lane >> 4) << 3);
    const int b_off = (((lane >> 4) << 3) + (lane & 7)) * RS +
                      (((lane >> 3) & 1) << 3);

    float acc[4][4][4];
    #pragma unroll
    for (int mi = 0; mi < 4; mi++)
        #pragma unroll
        for (int ni = 0; ni < 4; ni++)
            #pragma unroll
            for (int q = 0; q < 4; q++) acc[mi][ni][q] = 0.0f;

    const int KT = K / KTILE;

    auto issue = [&](int t, int st) {
        int k0 = t * KTILE;
        #pragma unroll
        for (int i = 0; i < 2; i++) {
            int id = tid + i * 256;
            int r  = id >> 2;
            int c  = id & 3;
            {
                const __nv_bfloat16* src = A + (size_t)(row0 + r) * K + k0 + c * 8;
                uint32_t dst = sbase + (uint32_t)(st * STE + r * RS) * 2 + c * 16;
                int sz = (row0 + r < M) ? 16 : 0;
                asm volatile("cp.async.cg.shared.global [%0], [%1], 16, %2;"
                             :: "r"(dst), "l"(src), "r"(sz));
            }
            {
                const __nv_bfloat16* src = B + (size_t)(col0 + r) * K + k0 + c * 8;
                uint32_t dst = sbase + (uint32_t)(st * STE + AE + r * RS) * 2 + c * 16;
                asm volatile("cp.async.cg.shared.global [%0], [%1], 16, %2;"
                             :: "r"(dst), "l"(src), "r"(16));
            }
        }
    };

    auto compute = [&](int st) {
        const uint32_t aBase = sbase + (uint32_t)(st * STE) * 2;
        const uint32_t bBase = sbase + (uint32_t)(st * STE + AE) * 2;
        #pragma unroll
        for (int ks = 0; ks < KTILE; ks += 16) {
            uint32_t af[4][4];
            #pragma unroll
            for (int mi = 0; mi < 4; mi++) {
                uint32_t addr = aBase +
                    (uint32_t)((wm + mi * 16) * RS + ks + a_off) * 2;
                asm volatile(
                    "ldmatrix.sync.aligned.m8n8.x4.shared.b16 "
                    "{%0,%1,%2,%3}, [%4];"
                    : "=r"(af[mi][0]), "=r"(af[mi][1]),
                      "=r"(af[mi][2]), "=r"(af[mi][3])
                    : "r"(addr));
            }
            uint32_t bfr[4][2];
            #pragma unroll
            for (int p = 0; p < 2; p++) {
                uint32_t addr = bBase +
                    (uint32_t)((wn + p * 16) * RS + ks + b_off) * 2;
                asm volatile(
                    "ldmatrix.sync.aligned.m8n8.x4.shared.b16 "
                    "{%0,%1,%2,%3}, [%4];"
                    : "=r"(bfr[2 * p][0]), "=r"(bfr[2 * p][1]),
                      "=r"(bfr[2 * p + 1][0]), "=r"(bfr[2 * p + 1][1])
                    : "r"(addr));
            }
            #pragma unroll
            for (int mi = 0; mi < 4; mi++)
                #pragma unroll
                for (int ni = 0; ni < 4; ni++) {
                    float* d = acc[mi][ni];
                    asm volatile(
                        "mma.sync.aligned.m16n8k16.row.col.f32.bf16.bf16.f32 "
                        "{%0,%1,%2,%3},{%4,%5,%6,%7},{%8,%9},{%0,%1,%2,%3};"
                        : "+f"(d[0]), "+f"(d[1]), "+f"(d[2]), "+f"(d[3])
                        : "r"(af[mi][0]), "r"(af[mi][1]),
                          "r"(af[mi][2]), "r"(af[mi][3]),
                          "r"(bfr[ni][0]), "r"(bfr[ni][1]));
                }
        }
    };

    issue(0, 0);
    asm volatile("cp.async.commit_group;" ::: "memory");
    issue(1, 1);
    asm volatile("cp.async.commit_group;" ::: "memory");
    issue(2, 2);
    asm volatile("cp.async.commit_group;" ::: "memory");

    for (int t4 = 0; t4 < KT; t4 += 4) {
        #pragma unroll
        for (int s = 0; s < 4; s++) {
            int t = t4 + s;
            asm volatile("cp.async.wait_group 2;" ::: "memory");
            __syncthreads();
            if (t + 3 < KT) issue(t + 3, (s + 3) & 3);
            asm volatile("cp.async.commit_group;" ::: "memory");
            compute(s);
        }
    }

    #pragma unroll
    for (int mi = 0; mi < 4; mi++) {
        #pragma unroll
        for (int half = 0; half < 2; half++) {
            int gr = row0 + wm + mi * 16 + fr + half * 8;
            if (gr >= M) continue;
            #pragma unroll
            for (int ni = 0; ni < 4; ni++) {
                int gc = col0 + wn + ni * 8 + 2 * fc;
                float2 v;
                v.x = acc[mi][ni][half * 2 + 0] + bias[gc + 0];
                v.y = acc[mi][ni][half * 2 + 1] + bias[gc + 1];
                if (RELU_OUT) {
                    v.x = fmaxf(v.x, 0.f);
                    v.y = fmaxf(v.y, 0.f);
                }
                if (RES) {
                    float2 r = *(const float2*)(res + (size_t)gr * N + gc);
                    v.x += r.x; v.y += r.y;
                }
                if (OUT_BF16) {
                    __nv_bfloat162 h = __float22bfloat162_rn(v);
                    *(uint32_t*)((__nv_bfloat16*)Cv + (size_t)gr * N + gc) =
                        *(uint32_t*)&h;
                } else {
                    *(float2*)((float*)Cv + (size_t)gr * N + gc) = v;
                }
            }
        }
    }
}

// ---------------- fused edge gather (bf16, packed K|V, 4 edges/warp) ---------
// 8-lane groups, one edge per group. Lane loads uint4 (8 bf16):
// sublanes 0-3 carry K32, 4-7 carry V32 (packed layout: ecol = h*64 + sub*8).
// Dot: 3 shfl steps within group; groups merged at the end (2 full-warp steps).
__device__ __forceinline__ float2 bf2f(uint32_t u) {
    return __bfloat1622float2(*(__nv_bfloat162*)&u);
}

__global__ __launch_bounds__(256)
void edge_gather_kernel(const __nv_bfloat16* __restrict__ KQV,
                        int r0, int nNodes)
{
    int w = (blockIdx.x * blockDim.x + threadIdx.x) >> 5;
    if (w >= nNodes * HEADS) return;
    const int lane = threadIdx.x & 31;
    const int grp  = lane >> 3;              // 0..3
    const int sub  = lane & 7;               // 0..7
    const unsigned gmask = 0xFFu << (grp * 8);
    const int r = (w >> 3) + r0;
    const int h = w & 7;

    // q octet for K sublanes (uniform load; V sublanes ignore it)
    uint4 qraw = *(const uint4*)(KQV + (size_t)r * KQVS + 512 + h * 32 +
                                 (sub & 3) * 8);
    const float2 q0 = bf2f(qraw.x), q1 = bf2f(qraw.y);
    const float2 q2 = bf2f(qraw.z), q3 = bf2f(qraw.w);
    const bool kSub = sub < 4;

    const int beg = g_off[r];
    const int end = g_off[r + 1];
    const size_t ecol = h * 64 + sub * 8;    // sub<4: K octet, sub>=4: V octet

    float denom = 0.f;
    float acc[8] = {0.f, 0.f, 0.f, 0.f, 0.f, 0.f, 0.f, 0.f};

    int i = beg + grp;
    for (; i + 4 < end; i += 8) {            // edges i and i+4 for this group
        int sA = g_csr[i];
        int sB = g_csr[i + 4];
        uint4 rA = *(const uint4*)(KQV + (size_t)sA * KQVS + ecol);
        uint4 rB = *(const uint4*)(KQV + (size_t)sB * KQVS + ecol);
        float2 a0 = bf2f(rA.x), a1 = bf2f(rA.y), a2 = bf2f(rA.z), a3 = bf2f(rA.w);
        float2 b0 = bf2f(rB.x), b1 = bf2f(rB.y), b2 = bf2f(rB.z), b3 = bf2f(rB.w);
        float dA = 0.f, dB = 0.f;
        if (kSub) {
            dA = fmaf(q3.y, a3.y, fmaf(q3.x, a3.x, fmaf(q2.y, a2.y,
                 fmaf(q2.x, a2.x, fmaf(q1.y, a1.y, fmaf(q1.x, a1.x,
                 fmaf(q0.y, a0.y, q0.x * a0.x)))))));
            dB = fmaf(q3.y, b3.y, fmaf(q3.x, b3.x, fmaf(q2.y, b2.y,
                 fmaf(q2.x, b2.x, fmaf(q1.y, b1.y, fmaf(q1.x, b1.x,
                 fmaf(q0.y, b0.y, q0.x * b0.x)))))));
        }
        #pragma unroll
        for (int m = 4; m; m >>= 1) {
            dA += __shfl_xor_sync(gmask, dA, m);
            dB += __shfl_xor_sync(gmask, dB, m);
        }
        float wA = __expf(dA * 0.17677669529663688f);
        float wB = __expf(dB * 0.17677669529663688f);
        denom += wA + wB;
        acc[0] = fmaf(wA, a0.x, acc[0]); acc[1] = fmaf(wA, a0.y, acc[1]);
        acc[2] = fmaf(wA, a1.x, acc[2]); acc[3] = fmaf(wA, a1.y, acc[3]);
        acc[4] = fmaf(wA, a2.x, acc[4]); acc[5] = fmaf(wA, a2.y, acc[5]);
        acc[6] = fmaf(wA, a3.x, acc[6]); acc[7] = fmaf(wA, a3.y, acc[7]);
        acc[0] = fmaf(wB, b0.x, acc[0]); acc[1] = fmaf(wB, b0.y, acc[1]);
        acc[2] = fmaf(wB, b1.x, acc[2]); acc[3] = fmaf(wB, b1.y, acc[3]);
        acc[4] = fmaf(wB, b2.x, acc[4]); acc[5] = fmaf(wB, b2.y, acc[5]);
        acc[6] = fmaf(wB, b3.x, acc[6]); acc[7] = fmaf(wB, b3.y, acc[7]);
    }
    for (; i < end; i += 4) {
        int s = g_csr[i];
        uint4 raw = *(const uint4*)(KQV + (size_t)s * KQVS + ecol);
        float2 a0 = bf2f(raw.x), a1 = bf2f(raw.y);
        float2 a2 = bf2f(raw.z), a3 = bf2f(raw.w);
        float d = 0.f;
        if (kSub)
            d = fmaf(q3.y, a3.y, fmaf(q3.x, a3.x, fmaf(q2.y, a2.y,
                fmaf(q2.x, a2.x, fmaf(q1.y, a1.y, fmaf(q1.x, a1.x,
                fmaf(q0.y, a0.y, q0.x * a0.x)))))));
        #pragma unroll
        for (int m = 4; m; m >>= 1)
            d += __shfl_xor_sync(gmask, d, m);
        float wg = __expf(d * 0.17677669529663688f);
        denom += wg;
        acc[0] = fmaf(wg, a0.x, acc[0]); acc[1] = fmaf(wg, a0.y, acc[1]);
        acc[2] = fmaf(wg, a1.x, acc[2]); acc[3] = fmaf(wg, a1.y, acc[3]);
        acc[4] = fmaf(wg, a2.x, acc[4]); acc[5] = fmaf(wg, a2.y, acc[5]);
        acc[6] = fmaf(wg, a3.x, acc[6]); acc[7] = fmaf(wg, a3.y, acc[7]);
    }

    // merge the four groups (sub position preserved -> V accs merge with V accs)
    __syncwarp();
    denom += __shfl_xor_sync(0xffffffffu, denom, 8);
    denom += __shfl_xor_sync(0xffffffffu, denom, 16);
    #pragma unroll
    for (int j = 0; j < 8; j++) {
        acc[j] += __shfl_xor_sync(0xffffffffu, acc[j], 8);
        acc[j] += __shfl_xor_sync(0xffffffffu, acc[j], 16);
    }

    if (lane >= 4 && lane < 8) {             // group 0, V sublanes
        float o[8];
        if (denom > 0.f) {
            float inv = 1.0f / denom;
            #pragma unroll
            for (int j = 0; j < 8; j++) o[j] = fmaxf(acc[j] * inv, 0.f);
        } else {
            #pragma unroll
            for (int j = 0; j < 8; j++) o[j] = 0.f;
        }
        __nv_bfloat162 h0 = __float22bfloat162_rn(make_float2(o[0], o[1]));
        __nv_bfloat162 h1 = __float22bfloat162_rn(make_float2(o[2], o[3]));
        __nv_bfloat162 h2 = __float22bfloat162_rn(make_float2(o[4], o[5]));
        __nv_bfloat162 h3 = __float22bfloat162_rn(make_float2(o[6], o[7]));
        uint4 pk;
        pk.x = *(uint32_t*)&h0; pk.y = *(uint32_t*)&h1;
        pk.z = *(uint32_t*)&h2; pk.w = *(uint32_t*)&h3;
        *(uint4*)(g_aggb + (size_t)r * HD + h * 32 + (sub - 4) * 8) = pk;
    }
}

// ---------------- launch ----------------------------------------------------
extern "C" void kernel_launch(void* const* d_in, const int* in_sizes, int n_in,
                              void* d_out, int out_size)
{
    const float* x  = (const float*)d_in[0];
    const int*   ei = (const int*)d_in[1];
    const float* Wk = (const float*)d_in[2];
    const float* bk = (const float*)d_in[3];
    const float* Wq = (const float*)d_in[4];
    const float* bq = (const float*)d_in[5];
    const float* Wv = (const float*)d_in[6];
    const float* bv = (const float*)d_in[7];
    const float* Wa = (const float*)d_in[8];
    const float* ba = (const float*)d_in[9];
    const float* Wf = (const float*)d_in[10];
    const float* bf = (const float*)d_in[11];
    float* out = (float*)d_out;

    float *gBkqv;
    __nv_bfloat16 *gKQVb, *gXb, *gAggb, *gH1b, *gWtb;
    cudaGetSymbolAddress((void**)&gBkqv, g_bkqv);
    cudaGetSymbolAddress((void**)&gKQVb, g_kqvb);
    cudaGetSymbolAddress((void**)&gXb,   g_xb);
    cudaGetSymbolAddress((void**)&gAggb, g_aggb);
    cudaGetSymbolAddress((void**)&gH1b,  g_h1b);
    cudaGetSymbolAddress((void**)&gWtb,  g_wtb);

    cudaFuncSetAttribute(bf16gemm<false, true, false>,
                         cudaFuncAttributeMaxDynamicSharedMemorySize, GEMM_SMEM);
    cudaFuncSetAttribute(bf16gemm<true, true, false>,
                         cudaFuncAttributeMaxDynamicSharedMemorySize, GEMM_SMEM);
    cudaFuncSetAttribute(bf16gemm<true, false, true>,
                         cudaFuncAttributeMaxDynamicSharedMemorySize, GEMM_SMEM);

    static cudaStream_t s1 = nullptr;
    static cudaEvent_t evFork = nullptr, evCSR = nullptr,
                       evGA = nullptr, evS1 = nullptr;
    if (s1 == nullptr) {
        cudaStreamCreate(&s1);
        cudaEventCreateWithFlags(&evFork, cudaEventDisableTiming);
        cudaEventCreateWithFlags(&evCSR,  cudaEventDisableTiming);
        cudaEventCreateWithFlags(&evGA,   cudaEventDisableTiming);
        cudaEventCreateWithFlags(&evS1,   cudaEventDisableTiming);
    }

    const int MT  = (N_NODES + 127) / 128;   // 391 row tiles
    const int MTA = M_SPLIT / 128;           // 196
    const int MTB = MT - MTA;                // 195
    const int NA  = M_SPLIT;                 // 25088 rows (half A)
    const int NB  = N_NODES - M_SPLIT;       // 24912 rows (half B)

    // ---- fork: CSR build on s1, prep+KQV on s0
    cudaEventRecord(evFork, 0);
    cudaStreamWaitEvent(s1, evFork, 0);
    zero_cnt_kernel<<<(N_NODES + 255) / 256, 256, 0, s1>>>();
    hist_kernel<<<(N_EDGES + 255) / 256, 256, 0, s1>>>(ei);
    scan_kernel<<<1, 1024, 0, s1>>>();
    place_kernel<<<(N_EDGES + 255) / 256, 256, 0, s1>>>(ei);
    cudaEventRecord(evCSR, s1);

    wt_all_cvt_kernel<<<(786432 + 255) / 256, 256>>>(Wk, Wq, Wv, Wa, Wf);
    cvt_bf16_kernel<<<(N_NODES * D_EMB / 4 + 255) / 256, 256>>>(x, gXb,
                                                                N_NODES * D_EMB / 4);
    bias_concat_kernel<<<3, 256>>>(bk, bq, bv);

    dim3 gProj(KQVS / 128, MT);                     // (6, 391)
    bf16gemm<false, true, false><<<gProj, 256, GEMM_SMEM>>>(
        gXb, gWtb + OFF_WKQV, gBkqv, nullptr, gKQVb, N_NODES, KQVS, D_EMB);

    // ---- join CSR, then split-M pipelined tail chain
    cudaStreamWaitEvent(0, evCSR, 0);

    // gather half A on s0, signal s1
    edge_gather_kernel<<<(NA * HEADS * 32 + 255) / 256, 256>>>(gKQVb, 0, NA);
    cudaEventRecord(evGA, 0);

    // s1: attn-out A + ffn A (overlaps gather B / attn-out B on s0)
    cudaStreamWaitEvent(s1, evGA, 0);
    dim3 gAa(D_EMB / 128, MTA);
    bf16gemm<true, true, false><<<gAa, 256, GEMM_SMEM, s1>>>(
        gAggb, gWtb + OFF_WA, ba, nullptr, gH1b, NA, D_EMB, HD);
    dim3 gFa(D_EMB / 128, MTA);
    bf16gemm<true, false, true><<<gFa, 256, GEMM_SMEM, s1>>>(
        gH1b, gWtb + OFF_WF, bf, x, out, NA, D_EMB, D_EMB);
    cudaEventRecord(evS1, s1);

    // s0: gather B, attn-out B, ffn B
    edge_gather_kernel<<<(NB * HEADS * 32 + 255) / 256, 256>>>(gKQVb, NA, NB);
    dim3 gAb(D_EMB / 128, MTB);
    bf16gemm<true, true, false><<<gAb, 256, GEMM_SMEM>>>(
        gAggb + (size_t)NA * HD, gWtb + OFF_WA, ba, nullptr,
        gH1b + (size_t)NA * D_EMB, NB, D_EMB, HD);
    dim3 gFb(D_EMB / 128, MTB);
    bf16gemm<true, false, true><<<gFb, 256, GEMM_SMEM>>>(
        gH1b + (size_t)NA * D_EMB, gWtb + OFF_WF, bf,
        x + (size_t)NA * D_EMB, out + (size_t)NA * D_EMB, NB, D_EMB, D_EMB);

    // join s1 back before capture ends
    cudaStreamWaitEvent(0, evS1, 0);
}